// round 12
// baseline (speedup 1.0000x reference)
#include <cuda_runtime.h>
#include <cuda_fp16.h>
#include <cstdint>

// ---------------------------------------------------------------------------
// NeuroVPR SNN via mma.sync fp16 2-way exact-split (scale 2^6).
//  L1: 128Mx256N CTA tiles, 512 thr, 3-buf single-sync pipeline (R11-proven).
//  Fused per-t kernel: LIF1 (inline A-producer) -> L2 GEMM -> LIF2 ->
//    L3 GEMM (s2 stays in smem) -> LIF3 -> out.  s1/s2 never hit DRAM.
// ---------------------------------------------------------------------------

#define B_ 16384
#define T_ 3
#define D_ 2752
#define H_ 256
#define O_ 100

// ---- scratch ----
__device__ float g_h1[(size_t)B_ * T_ * H_];
__device__ float g_v1[(size_t)B_ * H_];
__device__ float g_v2[(size_t)B_ * H_];
__device__ float g_v3[(size_t)B_ * 128];
__device__ __half g_W1s[2 * H_ * D_];
__device__ __half g_W2s[2 * H_ * H_];
__device__ __half g_W3s[2 * 128 * H_];   // padded to 128 rows

#define WSCALE 64.0f
#define INV_S1 (1.0f / 4096.0f)   // L1: A and W both scaled 2^6
#define INV_S2 (1.0f / 64.0f)     // L2/3: only W scaled

// ======================= helpers =======================
__device__ __forceinline__ uint32_t smem_u32(const void* p) {
    uint32_t a;
    asm("{ .reg .u64 t; cvta.to.shared.u64 t, %1; cvt.u32.u64 %0, t; }"
        : "=r"(a) : "l"(p));
    return a;
}
#define CP_ASYNC16(dst, src) \
    asm volatile("cp.async.cg.shared.global [%0], [%1], 16;" :: "r"(dst), "l"(src))
#define CP_COMMIT() asm volatile("cp.async.commit_group;" ::: "memory")
#define CP_WAIT0() asm volatile("cp.async.wait_group 0;" ::: "memory")
#define CP_WAIT1() asm volatile("cp.async.wait_group 1;" ::: "memory")
#define LDSM4(r0, r1, r2, r3, addr) \
    asm volatile("ldmatrix.sync.aligned.m8n8.x4.shared.b16 {%0,%1,%2,%3}, [%4];" \
        : "=r"(r0), "=r"(r1), "=r"(r2), "=r"(r3) : "r"(addr))
#define MMA16816(d, a, b) \
    asm volatile("mma.sync.aligned.m16n8k16.row.col.f32.f16.f16.f32 " \
        "{%0,%1,%2,%3}, {%4,%5,%6,%7}, {%8,%9}, {%0,%1,%2,%3};" \
        : "+f"((d)[0]), "+f"((d)[1]), "+f"((d)[2]), "+f"((d)[3]) \
        : "r"((a)[0]), "r"((a)[1]), "r"((a)[2]), "r"((a)[3]), "r"((b)[0]), "r"((b)[1]))

__device__ __forceinline__ void split2(float x, __half& h, __half& l) {
    float xs = x * WSCALE;
    h = __float2half_rn(xs);
    l = __float2half_rn(xs - __half2float(h));
}
__device__ __forceinline__ uint32_t pack_h2(__half lo, __half hi) {
    return (uint32_t)__half_as_ushort(lo) | ((uint32_t)__half_as_ushort(hi) << 16);
}
__device__ __forceinline__ void lif_c(float hval, float vin, float& vout, float& sout) {
    float vn = __fadd_rn(vin, __fmul_rn(__fsub_rn(hval, vin), 0.5f));
    bool sp = (vn >= 1.0f);
    vout = sp ? 0.0f : vn;
    sout = sp ? 1.0f : 0.0f;
}
// swizzled byte offset inside an Rx32-f16 plane (row 64B = 4 x 16B chunks)
__device__ __forceinline__ uint32_t swz(int r, int c) {
    return (uint32_t)(r * 64 + ((c ^ ((r >> 1) & 3)) << 4));
}

// ======================= weight split kernels =======================
__global__ void split_w_kernel(const float* __restrict__ W, __half* dst, int n) {
    int i = blockIdx.x * 256 + threadIdx.x;
    __half h, l;
    split2(W[i], h, l);
    dst[i] = h; dst[i + n] = l;
}
__global__ void split_w3_kernel(const float* __restrict__ W3) {
    int i = blockIdx.x * 256 + threadIdx.x;      // over 128*H_
    int r = i >> 8, c = i & 255;
    float w = (r < O_) ? W3[r * H_ + c] : 0.0f;
    __half h, l;
    split2(w, h, l);
    g_W3s[i] = h; g_W3s[i + 128 * H_] = l;
}

// ======================= Layer-1 GEMM: 128Mx256N, 512 thr (R11) =============
#define NST1 (D_ / 32)            // 86
#define APL1 8192
#define AB1  (2 * APL1)
#define BPL1 16384
#define STG1 (AB1 + 2 * BPL1)     // 49152
#define SMEM1 (3 * STG1)          // 147456

__global__ void __launch_bounds__(512, 1) mma_gemm1(
    const float* __restrict__ Af32, const __half* __restrict__ Ws,
    const float* __restrict__ bias, float* __restrict__ Hout) {
    extern __shared__ char smem[];
    const uint32_t sb = smem_u32(smem);
    const int tid = threadIdx.x;
    const int lane = tid & 31;
    const int wid = tid >> 5;
    const int m0 = blockIdx.x * 128;
    const int mbase = (wid & 3) * 32;
    const int nbase = (wid >> 2) * 64;

    float acc[2][8][4];
#pragma unroll
    for (int i = 0; i < 2; ++i)
#pragma unroll
        for (int j = 0; j < 8; ++j)
#pragma unroll
            for (int k = 0; k < 4; ++k) acc[i][j][k] = 0.0f;

    float4 ra2[2];
    const int lr = tid >> 2, lc = tid & 3;

    auto ldg_A = [&](int ks) {
        const float* g = Af32 + (size_t)(m0 + lr) * D_ + ks * 32 + lc * 8;
        ra2[0] = *(const float4*)g;
        ra2[1] = *(const float4*)(g + 4);
    };
    auto sts_A_split = [&](int buf) {
        uint32_t ab = sb + buf * STG1;
        float x[8] = {ra2[0].x, ra2[0].y, ra2[0].z, ra2[0].w,
                      ra2[1].x, ra2[1].y, ra2[1].z, ra2[1].w};
        __half s0[8], s1[8];
#pragma unroll
        for (int j = 0; j < 8; ++j) split2(x[j], s0[j], s1[j]);
        uint32_t off = swz(lr, lc);
        uint4 v0 = make_uint4(pack_h2(s0[0], s0[1]), pack_h2(s0[2], s0[3]),
                              pack_h2(s0[4], s0[5]), pack_h2(s0[6], s0[7]));
        uint4 v1 = make_uint4(pack_h2(s1[0], s1[1]), pack_h2(s1[2], s1[3]),
                              pack_h2(s1[4], s1[5]), pack_h2(s1[6], s1[7]));
        asm volatile("st.shared.v4.b32 [%0], {%1,%2,%3,%4};" :: "r"(ab + off),
                     "r"(v0.x), "r"(v0.y), "r"(v0.z), "r"(v0.w));
        asm volatile("st.shared.v4.b32 [%0], {%1,%2,%3,%4};" :: "r"(ab + APL1 + off),
                     "r"(v1.x), "r"(v1.y), "r"(v1.z), "r"(v1.w));
    };
    auto load_B = [&](int ks, int buf) {
        int kc = ks * 32;
        uint32_t bb = sb + buf * STG1 + AB1;
#pragma unroll
        for (int u = 0; u < 4; ++u) {
            int f = tid + u * 512;
            int s = f >> 10, rem = f & 1023, r = rem >> 2, c = rem & 3;
            const __half* src = Ws + (size_t)s * (H_ * D_) + (size_t)r * D_ + kc + c * 8;
            CP_ASYNC16(bb + s * BPL1 + swz(r, c), src);
        }
    };

    const int a_row = mbase + (lane & 7) + ((lane >> 3) & 1) * 8;
    const int a_chb = (lane >> 4);
    const int b_row = nbase + (lane & 7) + (lane >> 4) * 8;
    const int b_chb = ((lane >> 3) & 1);

    auto ldsmA = [&](uint32_t ab, int plane, int kk, uint32_t* dst) {
#pragma unroll
        for (int ma = 0; ma < 2; ++ma) {
            uint32_t ad = ab + plane * APL1 + swz(a_row + ma * 16, kk * 2 + a_chb);
            LDSM4(dst[ma * 4 + 0], dst[ma * 4 + 1], dst[ma * 4 + 2], dst[ma * 4 + 3], ad);
        }
    };
    auto ldsmB = [&](uint32_t bb, int pb, int kk, uint32_t* dst) {
#pragma unroll
        for (int h = 0; h < 4; ++h) {
            uint32_t bd = bb + pb * BPL1 + swz(b_row + h * 16, kk * 2 + b_chb);
            LDSM4(dst[h * 4 + 0], dst[h * 4 + 1], dst[h * 4 + 2], dst[h * 4 + 3], bd);
        }
    };
    auto mmaP = [&](const uint32_t* a, const uint32_t* b) {
#pragma unroll
        for (int ma = 0; ma < 2; ++ma)
#pragma unroll
            for (int na = 0; na < 8; ++na)
                MMA16816(acc[ma][na], &a[ma * 4], &b[na * 2]);
    };

    auto compute = [&](int buf) {
        uint32_t ab = sb + buf * STG1;
        uint32_t bb = ab + AB1;
        uint32_t a0[8], a1[8], a0n[8], bx[16], by[16];
        ldsmA(ab, 0, 0, a0);
        ldsmA(ab, 1, 0, a1);
        ldsmB(bb, 0, 0, bx);
        ldsmB(bb, 1, 0, by);
        mmaP(a0, bx);
        mmaP(a1, bx);
        ldsmA(ab, 0, 1, a0n);
        ldsmA(ab, 1, 1, a1);
        ldsmB(bb, 0, 1, bx);
        mmaP(a0, by);
        ldsmB(bb, 1, 1, by);
        mmaP(a0n, bx);
        mmaP(a1, bx);
        mmaP(a0n, by);
    };

    ldg_A(0); sts_A_split(0);
    load_B(0, 0); CP_COMMIT();
    load_B(1, 1); CP_COMMIT();
    ldg_A(1);

    int buf = 0;
    for (int ks = 0; ks < NST1; ++ks) {
        int b1 = (buf + 1 == 3) ? 0 : buf + 1;
        int b2 = (b1 + 1 == 3) ? 0 : b1 + 1;
        if (ks + 1 < NST1) sts_A_split(b1);
        if (ks + 2 < NST1) ldg_A(ks + 2);
        if (ks + 1 < NST1) { CP_WAIT1(); } else { CP_WAIT0(); }
        __syncthreads();
        if (ks + 2 < NST1) { load_B(ks + 2, b2); CP_COMMIT(); }
        compute(buf);
        buf = b1;
    }

#pragma unroll
    for (int ma = 0; ma < 2; ++ma) {
        int row0 = m0 + mbase + ma * 16 + (lane >> 2);
#pragma unroll
        for (int na = 0; na < 8; ++na) {
            int col0 = nbase + na * 8 + (lane & 3) * 2;
            const float* a4 = acc[ma][na];
#pragma unroll
            for (int h = 0; h < 2; ++h) {
                int row = row0 + h * 8;
                float cx = __fmul_rn(a4[h * 2 + 0], INV_S1);
                float cy = __fmul_rn(a4[h * 2 + 1], INV_S1);
                float2 o = make_float2(__fadd_rn(cx, bias[col0]),
                                       __fadd_rn(cy, bias[col0 + 1]));
                *(float2*)(Hout + (size_t)row * H_ + col0) = o;
            }
        }
    }
}

// ======== Fused per-t kernel: LIF1 -> L2 GEMM -> LIF2 -> L3 GEMM -> LIF3 ====
// 128 CTAs x 512 thr; tile 128M x 256N (phase 1), then 128M x 128N (phase 2).
#define NSTF (H_ / 32)            // 8
#define SAF  8192                 // A spikes: 128 x 64B (1 plane)
#define SBF  32768                // B: 2 planes x 256 x 64B
#define STGF (SAF + SBF)          // 40960
#define S2OFF (3 * STGF)          // 122880  (s2: 8 chunks x 8192 = 64KB)
#define B3OFF (S2OFF + 65536)     // 188416  (W3 stages: 2 x 16384)
#define SMEMF (B3OFF + 2 * 16384) // 221184

__global__ void __launch_bounds__(512, 1) fused_l23(
    const float* __restrict__ h1, const __half* __restrict__ W2s,
    const __half* __restrict__ W3s, const float* __restrict__ b2,
    const float* __restrict__ b3, float* __restrict__ v1,
    float* __restrict__ v2, float* __restrict__ v3,
    float* __restrict__ out, int t) {
    extern __shared__ char smem[];
    const uint32_t sb = smem_u32(smem);
    const int tid = threadIdx.x;
    const int lane = tid & 31;
    const int wid = tid >> 5;
    const int m0 = blockIdx.x * 128;
    const int mbase = (wid & 3) * 32;
    const int nbase = (wid >> 2) * 64;
    const int lr = tid >> 2, lc = tid & 3;

    float acc[2][8][4];
#pragma unroll
    for (int i = 0; i < 2; ++i)
#pragma unroll
        for (int j = 0; j < 8; ++j)
#pragma unroll
            for (int k = 0; k < 4; ++k) acc[i][j][k] = 0.0f;

    float4 rh[2], rv[2];

    // A producer: read h1 (+v1), LIF1, write v1 back, spikes -> smem fp16
    auto ldg_hv = [&](int ks) {
        const float* gh = h1 + ((size_t)(m0 + lr) * 3 + t) * H_ + ks * 32 + lc * 8;
        rh[0] = *(const float4*)gh;
        rh[1] = *(const float4*)(gh + 4);
        if (t > 0) {
            const float* gv = v1 + (size_t)(m0 + lr) * H_ + ks * 32 + lc * 8;
            rv[0] = *(const float4*)gv;
            rv[1] = *(const float4*)(gv + 4);
        } else {
            rv[0] = rv[1] = make_float4(0.f, 0.f, 0.f, 0.f);
        }
    };
    auto sts_lif1 = [&](int ks, int buf) {
        float hx[8] = {rh[0].x, rh[0].y, rh[0].z, rh[0].w,
                       rh[1].x, rh[1].y, rh[1].z, rh[1].w};
        float vx[8] = {rv[0].x, rv[0].y, rv[0].z, rv[0].w,
                       rv[1].x, rv[1].y, rv[1].z, rv[1].w};
        float vo[8], so[8];
#pragma unroll
        for (int j = 0; j < 8; ++j) lif_c(hx[j], vx[j], vo[j], so[j]);
        float* gv = v1 + (size_t)(m0 + lr) * H_ + ks * 32 + lc * 8;
        *(float4*)gv = make_float4(vo[0], vo[1], vo[2], vo[3]);
        *(float4*)(gv + 4) = make_float4(vo[4], vo[5], vo[6], vo[7]);
        uint4 vv = make_uint4(
            pack_h2(__float2half_rn(so[0]), __float2half_rn(so[1])),
            pack_h2(__float2half_rn(so[2]), __float2half_rn(so[3])),
            pack_h2(__float2half_rn(so[4]), __float2half_rn(so[5])),
            pack_h2(__float2half_rn(so[6]), __float2half_rn(so[7])));
        uint32_t ab = sb + buf * STGF;
        asm volatile("st.shared.v4.b32 [%0], {%1,%2,%3,%4};" :: "r"(ab + swz(lr, lc)),
                     "r"(vv.x), "r"(vv.y), "r"(vv.z), "r"(vv.w));
    };
    auto load_B2 = [&](int ks, int buf) {
        uint32_t bb = sb + buf * STGF + SAF;
#pragma unroll
        for (int u = 0; u < 4; ++u) {
            int f = tid + u * 512;
            int s = f >> 10, rem = f & 1023, r = rem >> 2, c = rem & 3;
            const __half* src = W2s + (size_t)s * (H_ * H_) + (size_t)r * H_ + ks * 32 + c * 8;
            CP_ASYNC16(bb + s * 16384 + swz(r, c), src);
        }
    };

    const int a_row = mbase + (lane & 7) + ((lane >> 3) & 1) * 8;
    const int a_chb = (lane >> 4);
    const int b_row = nbase + (lane & 7) + (lane >> 4) * 8;
    const int b_chb = ((lane >> 3) & 1);

    auto compute1 = [&](int buf) {
        uint32_t ab = sb + buf * STGF;
        uint32_t bb = ab + SAF;
#pragma unroll
        for (int kk = 0; kk < 2; ++kk) {
            uint32_t a[8];
#pragma unroll
            for (int ma = 0; ma < 2; ++ma) {
                uint32_t ad = ab + swz(a_row + ma * 16, kk * 2 + a_chb);
                LDSM4(a[ma * 4 + 0], a[ma * 4 + 1], a[ma * 4 + 2], a[ma * 4 + 3], ad);
            }
#pragma unroll
            for (int pb = 0; pb < 2; ++pb) {
                uint32_t b[16];
#pragma unroll
                for (int h = 0; h < 4; ++h) {
                    uint32_t bd = bb + pb * 16384 + swz(b_row + h * 16, kk * 2 + b_chb);
                    LDSM4(b[h * 4 + 0], b[h * 4 + 1], b[h * 4 + 2], b[h * 4 + 3], bd);
                }
#pragma unroll
                for (int ma = 0; ma < 2; ++ma)
#pragma unroll
                    for (int na = 0; na < 8; ++na)
                        MMA16816(acc[ma][na], &a[ma * 4], &b[na * 2]);
            }
        }
    };

    // ---- phase 1 pipeline ----
    ldg_hv(0); sts_lif1(0, 0);
    load_B2(0, 0); CP_COMMIT();
    load_B2(1, 1); CP_COMMIT();
    ldg_hv(1);

    int buf = 0;
    for (int ks = 0; ks < NSTF; ++ks) {
        int b1 = (buf + 1 == 3) ? 0 : buf + 1;
        int b2b = (b1 + 1 == 3) ? 0 : b1 + 1;
        if (ks + 1 < NSTF) sts_lif1(ks + 1, b1);
        if (ks + 2 < NSTF) ldg_hv(ks + 2);
        if (ks + 1 < NSTF) { CP_WAIT1(); } else { CP_WAIT0(); }
        __syncthreads();
        if (ks + 2 < NSTF) { load_B2(ks + 2, b2b); CP_COMMIT(); }
        compute1(buf);
        buf = b1;
    }

    // ---- start W3 prefetch, then LIF2 epilogue -> s2 in smem ----
    auto load_B3 = [&](int ks, int bf) {
        uint32_t bb = sb + B3OFF + bf * 16384;
#pragma unroll
        for (int u = 0; u < 2; ++u) {
            int f = tid + u * 512;
            int s = f >> 9, rem = f & 511, r = rem >> 2, c = rem & 3;
            const __half* src = W3s + (size_t)s * (128 * H_) + (size_t)r * H_ + ks * 32 + c * 8;
            CP_ASYNC16(bb + s * 8192 + swz(r, c), src);
        }
    };
    load_B3(0, 0); CP_COMMIT();

#pragma unroll
    for (int ma = 0; ma < 2; ++ma) {
        int row0 = m0 + mbase + ma * 16 + (lane >> 2);
#pragma unroll
        for (int na = 0; na < 8; ++na) {
            int col0 = nbase + na * 8 + (lane & 3) * 2;
            const float* a4 = acc[ma][na];
#pragma unroll
            for (int h = 0; h < 2; ++h) {
                int row = row0 + h * 8;
                float cx = __fmul_rn(a4[h * 2 + 0], INV_S2);
                float cy = __fmul_rn(a4[h * 2 + 1], INV_S2);
                float hx = __fadd_rn(cx, b2[col0]);
                float hy = __fadd_rn(cy, b2[col0 + 1]);
                size_t idx = (size_t)row * H_ + col0;
                float2 v = (t == 0) ? make_float2(0.f, 0.f) : *(float2*)(v2 + idx);
                float vox, voy, sox, soy;
                lif_c(hx, v.x, vox, sox);
                lif_c(hy, v.y, voy, soy);
                *(float2*)(v2 + idx) = make_float2(vox, voy);
                // s2 -> smem, chunked 32-k swizzled tiles
                int rloc = row - m0;
                int chunk = col0 >> 5, c32 = col0 & 31;
                uint32_t addr = sb + S2OFF + chunk * 8192 + swz(rloc, c32 >> 3) + (c32 & 7) * 2;
                uint32_t pk = pack_h2(__float2half_rn(sox), __float2half_rn(soy));
                asm volatile("st.shared.b32 [%0], %1;" :: "r"(addr), "r"(pk));
            }
        }
    }

    // ---- phase 2: D3 = s2 @ W3^T (K=256, N=128/100) ----
    float acc3[2][4][4];
#pragma unroll
    for (int i = 0; i < 2; ++i)
#pragma unroll
        for (int j = 0; j < 4; ++j)
#pragma unroll
            for (int k = 0; k < 4; ++k) acc3[i][j][k] = 0.0f;

    const int mbase2 = (wid & 3) * 32;
    const int nbase2 = (wid >> 2) * 32;
    const int a2_row = mbase2 + (lane & 7) + ((lane >> 3) & 1) * 8;
    const int b3_row = nbase2 + (lane & 7) + (lane >> 4) * 8;

    for (int ks = 0; ks < NSTF; ++ks) {
        CP_WAIT0();
        __syncthreads();   // (first iter also publishes s2 + B3(0))
        if (ks + 1 < NSTF) { load_B3(ks + 1, (ks + 1) & 1); CP_COMMIT(); }
        uint32_t abase = sb + S2OFF + ks * 8192;
        uint32_t bbase = sb + B3OFF + (ks & 1) * 16384;
#pragma unroll
        for (int kk = 0; kk < 2; ++kk) {
            uint32_t a[8];
#pragma unroll
            for (int ma = 0; ma < 2; ++ma) {
                uint32_t ad = abase + swz(a2_row + ma * 16, kk * 2 + a_chb);
                LDSM4(a[ma * 4 + 0], a[ma * 4 + 1], a[ma * 4 + 2], a[ma * 4 + 3], ad);
            }
#pragma unroll
            for (int pb = 0; pb < 2; ++pb) {
                uint32_t b[8];
#pragma unroll
                for (int h = 0; h < 2; ++h) {
                    uint32_t bd = bbase + pb * 8192 + swz(b3_row + h * 16, kk * 2 + b_chb);
                    LDSM4(b[h * 4 + 0], b[h * 4 + 1], b[h * 4 + 2], b[h * 4 + 3], bd);
                }
#pragma unroll
                for (int ma = 0; ma < 2; ++ma)
#pragma unroll
                    for (int na = 0; na < 4; ++na)
                        MMA16816(acc3[ma][na], &a[ma * 4], &b[na * 2]);
            }
        }
    }

    // ---- LIF3 epilogue -> out ----
#pragma unroll
    for (int ma = 0; ma < 2; ++ma) {
        int row0 = m0 + mbase2 + ma * 16 + (lane >> 2);
#pragma unroll
        for (int na = 0; na < 4; ++na) {
            int col0 = nbase2 + na * 8 + (lane & 3) * 2;
            if (col0 < O_) {
                const float* a4 = acc3[ma][na];
#pragma unroll
                for (int h = 0; h < 2; ++h) {
                    int row = row0 + h * 8;
                    float cx = __fmul_rn(a4[h * 2 + 0], INV_S2);
                    float cy = __fmul_rn(a4[h * 2 + 1], INV_S2);
                    float hx = __fadd_rn(cx, b3[col0]);
                    float hy = __fadd_rn(cy, b3[col0 + 1]);
                    size_t vidx = (size_t)row * 128 + col0;
                    float2 v = (t == 0) ? make_float2(0.f, 0.f) : *(float2*)(v3 + vidx);
                    float vox, voy, sox, soy;
                    lif_c(hx, v.x, vox, sox);
                    lif_c(hy, v.y, voy, soy);
                    *(float2*)(v3 + vidx) = make_float2(vox, voy);
                    *(float2*)(out + (size_t)row * O_ + col0) = make_float2(sox, soy);
                }
            }
        }
    }
}

extern "C" void kernel_launch(void* const* d_in, const int* in_sizes, int n_in,
                              void* d_out, int out_size) {
    const float* dvs = (const float*)d_in[0];
    const float* W1  = (const float*)d_in[1];
    const float* b1  = (const float*)d_in[2];
    const float* W2  = (const float*)d_in[3];
    const float* b2  = (const float*)d_in[4];
    const float* W3  = (const float*)d_in[5];
    const float* b3  = (const float*)d_in[6];
    float* out = (float*)d_out;

    float *h1, *v1, *v2, *v3;
    __half *w1s, *w2s, *w3s;
    cudaGetSymbolAddress((void**)&h1, g_h1);
    cudaGetSymbolAddress((void**)&v1, g_v1);
    cudaGetSymbolAddress((void**)&v2, g_v2);
    cudaGetSymbolAddress((void**)&v3, g_v3);
    cudaGetSymbolAddress((void**)&w1s, g_W1s);
    cudaGetSymbolAddress((void**)&w2s, g_W2s);
    cudaGetSymbolAddress((void**)&w3s, g_W3s);

    cudaFuncSetAttribute(mma_gemm1, cudaFuncAttributeMaxDynamicSharedMemorySize, SMEM1);
    cudaFuncSetAttribute(fused_l23, cudaFuncAttributeMaxDynamicSharedMemorySize, SMEMF);

    // weight splits (exact 2-way fp16, scale 2^6)
    split_w_kernel<<<(H_ * D_) / 256, 256>>>(W1, w1s, H_ * D_);
    split_w_kernel<<<(H_ * H_) / 256, 256>>>(W2, w2s, H_ * H_);
    split_w3_kernel<<<(128 * H_) / 256, 256>>>(W3);

    // layer 1, all timesteps: [B*T, D] @ W1^T -> g_h1  (128M x 256N tiles)
    mma_gemm1<<<(B_ * T_) / 128, 512, SMEM1>>>(dvs, w1s, b1, h1);

    // fused LIF1+L2+LIF2+L3+LIF3 per timestep
    for (int t = 0; t < T_; ++t) {
        fused_l23<<<B_ / 128, 512, SMEMF>>>(h1, w2s, w3s, b2, b3,
                                            v1, v2, v3, out, t);
    }
}